// round 8
// baseline (speedup 1.0000x reference)
#include <cuda_runtime.h>
#include <cuda_fp16.h>
#include <cstdint>

#define N_NODES 200000
#define DIM     64
#define NNZ_E   6400000
#define NE      (N_NODES * DIM)
#define SCAN_CHUNK 2048
#define SCAN_NBLK  ((N_NODES + SCAN_CHUNK - 1) / SCAN_CHUNK)   // 98

// Scratch: __device__ globals (allocation-free rule). ~154 MB.
__device__ __half g_h[NE];              // 25.6 MB  h = logmap0(x)
__device__ __half g_m1[NE];             // 25.6 MB  m1 = A h
__device__ __half g_m2[NE];             // 25.6 MB  m2 = A m1
__device__ __half g_m3[NE];             // 25.6 MB  m3 = A m2
__device__ int2   g_cv[NNZ_E];          // 51.2 MB  (col, val-bits) row-grouped
__device__ int    g_cnt[N_NODES];
__device__ int    g_rowptr[N_NODES + 1];
__device__ int    g_off[N_NODES];
__device__ int    g_blksum[SCAN_NBLK];

// ---------------------------------------------------------------------------
// Launch 0: logmap0 (c=1) -> fp16 h ; also zeroes histogram counters
// ---------------------------------------------------------------------------
__global__ void logmap_kernel(const float* __restrict__ x, __half2* __restrict__ h,
                              int* __restrict__ cnt) {
    int gi = blockIdx.x * blockDim.x + threadIdx.x;
    if (gi < N_NODES) cnt[gi] = 0;

    int row  = blockIdx.x * (blockDim.x >> 5) + (threadIdx.x >> 5);
    int lane = threadIdx.x & 31;
    if (row >= N_NODES) return;

    float2 v = reinterpret_cast<const float2*>(x + (size_t)row * DIM)[lane];
    float x0 = __shfl_sync(0xFFFFFFFFu, v.x, 0);
    float ss = v.y * v.y + (lane ? v.x * v.x : 0.0f);
    #pragma unroll
    for (int o = 16; o; o >>= 1) ss += __shfl_xor_sync(0xFFFFFFFFu, ss, o);

    float y_norm = fmaxf(sqrtf(ss), 1e-15f);
    float theta  = fmaxf(x0, 1.0f + 1e-7f);
    float s      = acoshf(theta) / y_norm;

    float2 o2;
    o2.x = lane ? s * v.x : 0.0f;
    o2.y = s * v.y;
    h[(size_t)row * 32 + lane] = __float22half2_rn(o2);
}

// ---------------------------------------------------------------------------
// Launch 1: histogram of row indices (int4 reads)
// ---------------------------------------------------------------------------
__global__ void hist_kernel(const int4* __restrict__ rows4, int* __restrict__ cnt) {
    int i = blockIdx.x * blockDim.x + threadIdx.x;
    for (; i < NNZ_E / 4; i += gridDim.x * blockDim.x) {
        int4 r = __ldg(rows4 + i);
        atomicAdd(&cnt[r.x], 1);
        atomicAdd(&cnt[r.y], 1);
        atomicAdd(&cnt[r.z], 1);
        atomicAdd(&cnt[r.w], 1);
    }
}

// ---------------------------------------------------------------------------
// Launch 2: per-block exclusive scan of 2048-chunks; totals -> blksum
// ---------------------------------------------------------------------------
__global__ void scan1_kernel(const int* __restrict__ cnt,
                             int* __restrict__ rowptr, int* __restrict__ blksum) {
    __shared__ int ws[32];
    __shared__ int carry_s;
    int tid = threadIdx.x, lane = tid & 31, wid = tid >> 5;
    int base0 = blockIdx.x * SCAN_CHUNK;
    if (tid == 0) carry_s = 0;
    __syncthreads();

    #pragma unroll
    for (int it = 0; it < SCAN_CHUNK / 1024; ++it) {
        int i = base0 + it * 1024 + tid;
        int v = (i < N_NODES) ? cnt[i] : 0;
        int x = v;
        #pragma unroll
        for (int o = 1; o < 32; o <<= 1) {
            int y = __shfl_up_sync(0xFFFFFFFFu, x, o);
            if (lane >= o) x += y;
        }
        if (lane == 31) ws[wid] = x;
        __syncthreads();
        if (wid == 0) {
            int s = ws[lane];
            #pragma unroll
            for (int o = 1; o < 32; o <<= 1) {
                int y = __shfl_up_sync(0xFFFFFFFFu, s, o);
                if (lane >= o) s += y;
            }
            ws[lane] = s;
        }
        __syncthreads();
        int carry = carry_s;
        int excl  = carry + (wid ? ws[wid - 1] : 0) + (x - v);
        if (i < N_NODES) rowptr[i] = excl;
        __syncthreads();
        if (tid == 0) carry_s = carry + ws[31];
        __syncthreads();
    }
    if (tid == 0) blksum[blockIdx.x] = carry_s;
}

// ---------------------------------------------------------------------------
// Launch 3: fused block-offset scan + apply
// ---------------------------------------------------------------------------
__global__ void scan3_kernel(int* __restrict__ rowptr, const int* __restrict__ blksum,
                             int* __restrict__ off) {
    __shared__ int boff[SCAN_NBLK];
    int tid = threadIdx.x, lane = tid & 31;
    if (tid < 32) {
        int carry = 0;
        for (int base = 0; base < SCAN_NBLK; base += 32) {
            int i = base + lane;
            int v = (i < SCAN_NBLK) ? blksum[i] : 0;
            int x = v;
            #pragma unroll
            for (int o = 1; o < 32; o <<= 1) {
                int y = __shfl_up_sync(0xFFFFFFFFu, x, o);
                if (lane >= o) x += y;
            }
            if (i < SCAN_NBLK) boff[i] = carry + x - v;
            carry += __shfl_sync(0xFFFFFFFFu, x, 31);
        }
    }
    __syncthreads();

    int i = blockIdx.x * blockDim.x + tid;
    for (; i < N_NODES; i += gridDim.x * blockDim.x) {
        int v = rowptr[i] + boff[i / SCAN_CHUNK];
        rowptr[i] = v;
        off[i]    = v;
    }
    if (blockIdx.x == 0 && tid == 0) rowptr[N_NODES] = NNZ_E;
}

// ---------------------------------------------------------------------------
// Launch 4: scatter (col,val) int2 into row-grouped cv; 2 edges/thread
// ---------------------------------------------------------------------------
__global__ void scatter_kernel(const int2* __restrict__ rows2, const int2* __restrict__ cols2,
                               const float2* __restrict__ vals2,
                               int* __restrict__ off, int2* __restrict__ cv) {
    int i = blockIdx.x * blockDim.x + threadIdx.x;
    for (; i < NNZ_E / 2; i += gridDim.x * blockDim.x) {
        int2   r = __ldg(rows2 + i);
        int2   c = __ldg(cols2 + i);
        float2 v = __ldg(vals2 + i);
        int p0 = atomicAdd(&off[r.x], 1);
        cv[p0] = make_int2(c.x, __float_as_int(v.x));
        int p1 = atomicAdd(&off[r.y], 1);
        cv[p1] = make_int2(c.y, __float_as_int(v.y));
    }
}

// ---------------------------------------------------------------------------
// Launches 5-8: CSR SpMM  dst = A * src  (fp16 gather, fp32 accumulate)
// Quad gather: lanes 8q..8q+7 handle edge e+q (q=0..3).
// Each lane loads a uint4 (16 B = dims 8*sub..+7); one LDG.128 covers a whole
// 128 B feature row -> 1 L2 line per gather, 4 edges per warp LDG instruction.
// Merge partials with shfl_xor(8) + shfl_xor(16); octet 0 stores.
// last layer fuses: out = 4*m1 + 5*m2 + 3*m3 + A*m3   (fp32)
// ---------------------------------------------------------------------------
__global__ void __launch_bounds__(256)
csr_spmm_kernel(const int* __restrict__ rowptr, const int2* __restrict__ cv,
                const uint4* __restrict__ src, uint4* __restrict__ dst,
                const uint4* __restrict__ m1, const uint4* __restrict__ m2,
                const uint4* __restrict__ m3, float4* __restrict__ out, int last) {
    int row  = blockIdx.x * 8 + (threadIdx.x >> 5);
    int lane = threadIdx.x & 31;
    if (row >= N_NODES) return;

    int beg = __ldg(rowptr + row);
    int end = __ldg(rowptr + row + 1);

    int quad = lane >> 3;    // which edge of the group of 4
    int sub  = lane & 7;     // which 16 B chunk of the 128 B row

    float a0 = 0.f, a1 = 0.f, a2 = 0.f, a3 = 0.f;
    float a4 = 0.f, a5 = 0.f, a6 = 0.f, a7 = 0.f;
    int e = beg;

    // 8 edges per iteration = 2 quad steps
    for (; e + 8 <= end; e += 8) {
        int2 w0 = __ldg(cv + e + quad);
        int2 w1 = __ldg(cv + e + 4 + quad);
        uint4 g0 = __ldg(src + (size_t)w0.x * 8 + sub);
        uint4 g1 = __ldg(src + (size_t)w1.x * 8 + sub);

        float v0 = __int_as_float(w0.y);
        float2 p;
        p = __half22float2(*reinterpret_cast<__half2*>(&g0.x)); a0 = fmaf(v0, p.x, a0); a1 = fmaf(v0, p.y, a1);
        p = __half22float2(*reinterpret_cast<__half2*>(&g0.y)); a2 = fmaf(v0, p.x, a2); a3 = fmaf(v0, p.y, a3);
        p = __half22float2(*reinterpret_cast<__half2*>(&g0.z)); a4 = fmaf(v0, p.x, a4); a5 = fmaf(v0, p.y, a5);
        p = __half22float2(*reinterpret_cast<__half2*>(&g0.w)); a6 = fmaf(v0, p.x, a6); a7 = fmaf(v0, p.y, a7);

        float v1 = __int_as_float(w1.y);
        p = __half22float2(*reinterpret_cast<__half2*>(&g1.x)); a0 = fmaf(v1, p.x, a0); a1 = fmaf(v1, p.y, a1);
        p = __half22float2(*reinterpret_cast<__half2*>(&g1.y)); a2 = fmaf(v1, p.x, a2); a3 = fmaf(v1, p.y, a3);
        p = __half22float2(*reinterpret_cast<__half2*>(&g1.z)); a4 = fmaf(v1, p.x, a4); a5 = fmaf(v1, p.y, a5);
        p = __half22float2(*reinterpret_cast<__half2*>(&g1.w)); a6 = fmaf(v1, p.x, a6); a7 = fmaf(v1, p.y, a7);
    }
    // masked quad tail
    for (; e < end; e += 4) {
        int idx = e + quad;
        int2 w = __ldg(cv + (idx < end ? idx : end - 1));
        float v = (idx < end) ? __int_as_float(w.y) : 0.0f;
        uint4 g = __ldg(src + (size_t)w.x * 8 + sub);
        float2 p;
        p = __half22float2(*reinterpret_cast<__half2*>(&g.x)); a0 = fmaf(v, p.x, a0); a1 = fmaf(v, p.y, a1);
        p = __half22float2(*reinterpret_cast<__half2*>(&g.y)); a2 = fmaf(v, p.x, a2); a3 = fmaf(v, p.y, a3);
        p = __half22float2(*reinterpret_cast<__half2*>(&g.z)); a4 = fmaf(v, p.x, a4); a5 = fmaf(v, p.y, a5);
        p = __half22float2(*reinterpret_cast<__half2*>(&g.w)); a6 = fmaf(v, p.x, a6); a7 = fmaf(v, p.y, a7);
    }

    // merge the 4 edge-parity partial sums (same dims across octets)
    #pragma unroll
    for (int o = 8; o <= 16; o <<= 1) {
        a0 += __shfl_xor_sync(0xFFFFFFFFu, a0, o);
        a1 += __shfl_xor_sync(0xFFFFFFFFu, a1, o);
        a2 += __shfl_xor_sync(0xFFFFFFFFu, a2, o);
        a3 += __shfl_xor_sync(0xFFFFFFFFu, a3, o);
        a4 += __shfl_xor_sync(0xFFFFFFFFu, a4, o);
        a5 += __shfl_xor_sync(0xFFFFFFFFu, a5, o);
        a6 += __shfl_xor_sync(0xFFFFFFFFu, a6, o);
        a7 += __shfl_xor_sync(0xFFFFFFFFu, a7, o);
    }

    if (quad == 0) {
        size_t o = (size_t)row * 8 + sub;
        if (!last) {
            __half2 h0 = __float22half2_rn(make_float2(a0, a1));
            __half2 h1 = __float22half2_rn(make_float2(a2, a3));
            __half2 h2 = __float22half2_rn(make_float2(a4, a5));
            __half2 h3 = __float22half2_rn(make_float2(a6, a7));
            uint4 r;
            r.x = *reinterpret_cast<uint32_t*>(&h0);
            r.y = *reinterpret_cast<uint32_t*>(&h1);
            r.z = *reinterpret_cast<uint32_t*>(&h2);
            r.w = *reinterpret_cast<uint32_t*>(&h3);
            dst[o] = r;
        } else {
            uint4 q1 = __ldg(m1 + o);
            uint4 q2 = __ldg(m2 + o);
            uint4 q3 = __ldg(m3 + o);
            float acc[8] = {a0, a1, a2, a3, a4, a5, a6, a7};
            const uint32_t* u1 = reinterpret_cast<const uint32_t*>(&q1);
            const uint32_t* u2 = reinterpret_cast<const uint32_t*>(&q2);
            const uint32_t* u3 = reinterpret_cast<const uint32_t*>(&q3);
            float ov[8];
            #pragma unroll
            for (int k = 0; k < 4; ++k) {
                float2 r1 = __half22float2(*reinterpret_cast<const __half2*>(&u1[k]));
                float2 r2 = __half22float2(*reinterpret_cast<const __half2*>(&u2[k]));
                float2 r3 = __half22float2(*reinterpret_cast<const __half2*>(&u3[k]));
                ov[2*k]   = fmaf(4.f, r1.x, fmaf(5.f, r2.x, fmaf(3.f, r3.x, acc[2*k])));
                ov[2*k+1] = fmaf(4.f, r1.y, fmaf(5.f, r2.y, fmaf(3.f, r3.y, acc[2*k+1])));
            }
            size_t ob = (size_t)row * 16 + sub * 2;
            out[ob]     = make_float4(ov[0], ov[1], ov[2], ov[3]);
            out[ob + 1] = make_float4(ov[4], ov[5], ov[6], ov[7]);
        }
    }
}

// ---------------------------------------------------------------------------
extern "C" void kernel_launch(void* const* d_in, const int* in_sizes, int n_in,
                              void* d_out, int out_size) {
    const float* x    = (const float*)d_in[0];
    const int*   rows = (const int*)  d_in[1];
    const int*   cols = (const int*)  d_in[2];
    const float* vals = (const float*)d_in[3];
    float*       out  = (float*)d_out;

    __half *h, *m1, *m2, *m3;
    int2   *cv;
    int    *cnt, *rowptr, *off, *blksum;
    cudaGetSymbolAddress((void**)&h,      g_h);
    cudaGetSymbolAddress((void**)&m1,     g_m1);
    cudaGetSymbolAddress((void**)&m2,     g_m2);
    cudaGetSymbolAddress((void**)&m3,     g_m3);
    cudaGetSymbolAddress((void**)&cv,     g_cv);
    cudaGetSymbolAddress((void**)&cnt,    g_cnt);
    cudaGetSymbolAddress((void**)&rowptr, g_rowptr);
    cudaGetSymbolAddress((void**)&off,    g_off);
    cudaGetSymbolAddress((void**)&blksum, g_blksum);

    const int ROW_BLOCKS = (N_NODES + 7) / 8;   // 25000

    logmap_kernel<<<ROW_BLOCKS, 256>>>(x, (__half2*)h, cnt);
    hist_kernel<<<4096, 256>>>((const int4*)rows, cnt);
    scan1_kernel<<<SCAN_NBLK, 1024>>>(cnt, rowptr, blksum);
    scan3_kernel<<<256, 256>>>(rowptr, blksum, off);
    scatter_kernel<<<8192, 256>>>((const int2*)rows, (const int2*)cols,
                                  (const float2*)vals, off, cv);

    csr_spmm_kernel<<<ROW_BLOCKS, 256>>>(rowptr, cv, (const uint4*)h,  (uint4*)m1,
                                         nullptr, nullptr, nullptr, nullptr, 0);
    csr_spmm_kernel<<<ROW_BLOCKS, 256>>>(rowptr, cv, (const uint4*)m1, (uint4*)m2,
                                         nullptr, nullptr, nullptr, nullptr, 0);
    csr_spmm_kernel<<<ROW_BLOCKS, 256>>>(rowptr, cv, (const uint4*)m2, (uint4*)m3,
                                         nullptr, nullptr, nullptr, nullptr, 0);
    csr_spmm_kernel<<<ROW_BLOCKS, 256>>>(rowptr, cv, (const uint4*)m3, nullptr,
                                         (const uint4*)m1, (const uint4*)m2,
                                         (const uint4*)m3, (float4*)out, 1);
}

// round 9
// speedup vs baseline: 1.0216x; 1.0216x over previous
#include <cuda_runtime.h>
#include <cuda_fp16.h>
#include <cstdint>

#define N_NODES 200000
#define DIM     64
#define NNZ_E   6400000
#define NE      (N_NODES * DIM)
#define SCAN_CHUNK 2048
#define SCAN_NBLK  ((N_NODES + SCAN_CHUNK - 1) / SCAN_CHUNK)   // 98

// Scratch: __device__ globals (allocation-free rule). ~154 MB.
// NOTE: g_cnt is zero at module load and is re-zeroed by the last layer kernel
// of every execution, so each run (correctness pass + every graph replay)
// begins with cnt == 0. No static guards; fully deterministic.
__device__ __half g_h[NE];              // 25.6 MB  h = logmap0(x)
__device__ __half g_m1[NE];             // 25.6 MB  m1 = A h
__device__ __half g_m2[NE];             // 25.6 MB  m2 = A m1
__device__ __half g_m3[NE];             // 25.6 MB  m3 = A m2
__device__ int2   g_cv[NNZ_E];          // 51.2 MB  (col, val-bits) row-grouped
__device__ int    g_cnt[N_NODES];
__device__ int    g_rowptr[N_NODES + 1];
__device__ int    g_off[N_NODES];
__device__ int    g_blksum[SCAN_NBLK];

// ---------------------------------------------------------------------------
// Launch 0: fused logmap0 + row histogram.
// logmap: one warp per row, lane owns dims {2l,2l+1}.
// hist:   first NNZ/4 threads each histogram one int4 of row indices.
// (cnt was zeroed by the previous execution's last layer kernel / module init)
// ---------------------------------------------------------------------------
__global__ void logmap_hist_kernel(const float* __restrict__ x, __half2* __restrict__ h,
                                   const int4* __restrict__ rows4, int* __restrict__ cnt) {
    int gi = blockIdx.x * blockDim.x + threadIdx.x;   // 6.4M threads
    if (gi < NNZ_E / 4) {
        int4 r = __ldg(rows4 + gi);
        atomicAdd(&cnt[r.x], 1);
        atomicAdd(&cnt[r.y], 1);
        atomicAdd(&cnt[r.z], 1);
        atomicAdd(&cnt[r.w], 1);
    }

    int row  = blockIdx.x * (blockDim.x >> 5) + (threadIdx.x >> 5);
    int lane = threadIdx.x & 31;
    if (row >= N_NODES) return;

    float2 v = reinterpret_cast<const float2*>(x + (size_t)row * DIM)[lane];
    float x0 = __shfl_sync(0xFFFFFFFFu, v.x, 0);
    float ss = v.y * v.y + (lane ? v.x * v.x : 0.0f);
    #pragma unroll
    for (int o = 16; o; o >>= 1) ss += __shfl_xor_sync(0xFFFFFFFFu, ss, o);

    float y_norm = fmaxf(sqrtf(ss), 1e-15f);
    float theta  = fmaxf(x0, 1.0f + 1e-7f);
    float s      = acoshf(theta) / y_norm;

    float2 o2;
    o2.x = lane ? s * v.x : 0.0f;
    o2.y = s * v.y;
    h[(size_t)row * 32 + lane] = __float22half2_rn(o2);
}

// ---------------------------------------------------------------------------
// Launch 1: per-block exclusive scan of 2048-chunks; totals -> blksum
// ---------------------------------------------------------------------------
__global__ void scan1_kernel(const int* __restrict__ cnt,
                             int* __restrict__ rowptr, int* __restrict__ blksum) {
    __shared__ int ws[32];
    __shared__ int carry_s;
    int tid = threadIdx.x, lane = tid & 31, wid = tid >> 5;
    int base0 = blockIdx.x * SCAN_CHUNK;
    if (tid == 0) carry_s = 0;
    __syncthreads();

    #pragma unroll
    for (int it = 0; it < SCAN_CHUNK / 1024; ++it) {
        int i = base0 + it * 1024 + tid;
        int v = (i < N_NODES) ? cnt[i] : 0;
        int x = v;
        #pragma unroll
        for (int o = 1; o < 32; o <<= 1) {
            int y = __shfl_up_sync(0xFFFFFFFFu, x, o);
            if (lane >= o) x += y;
        }
        if (lane == 31) ws[wid] = x;
        __syncthreads();
        if (wid == 0) {
            int s = ws[lane];
            #pragma unroll
            for (int o = 1; o < 32; o <<= 1) {
                int y = __shfl_up_sync(0xFFFFFFFFu, s, o);
                if (lane >= o) s += y;
            }
            ws[lane] = s;
        }
        __syncthreads();
        int carry = carry_s;
        int excl  = carry + (wid ? ws[wid - 1] : 0) + (x - v);
        if (i < N_NODES) rowptr[i] = excl;
        __syncthreads();
        if (tid == 0) carry_s = carry + ws[31];
        __syncthreads();
    }
    if (tid == 0) blksum[blockIdx.x] = carry_s;
}

// ---------------------------------------------------------------------------
// Launch 2: fused block-offset scan + apply
// ---------------------------------------------------------------------------
__global__ void scan3_kernel(int* __restrict__ rowptr, const int* __restrict__ blksum,
                             int* __restrict__ off) {
    __shared__ int boff[SCAN_NBLK];
    int tid = threadIdx.x, lane = tid & 31;
    if (tid < 32) {
        int carry = 0;
        for (int base = 0; base < SCAN_NBLK; base += 32) {
            int i = base + lane;
            int v = (i < SCAN_NBLK) ? blksum[i] : 0;
            int x = v;
            #pragma unroll
            for (int o = 1; o < 32; o <<= 1) {
                int y = __shfl_up_sync(0xFFFFFFFFu, x, o);
                if (lane >= o) x += y;
            }
            if (i < SCAN_NBLK) boff[i] = carry + x - v;
            carry += __shfl_sync(0xFFFFFFFFu, x, 31);
        }
    }
    __syncthreads();

    int i = blockIdx.x * blockDim.x + tid;
    for (; i < N_NODES; i += gridDim.x * blockDim.x) {
        int v = rowptr[i] + boff[i / SCAN_CHUNK];
        rowptr[i] = v;
        off[i]    = v;
    }
    if (blockIdx.x == 0 && tid == 0) rowptr[N_NODES] = NNZ_E;
}

// ---------------------------------------------------------------------------
// Launch 3: scatter (col,val) int2 into row-grouped cv; 4 edges/thread (ILP)
// ---------------------------------------------------------------------------
__global__ void scatter_kernel(const int4* __restrict__ rows4, const int4* __restrict__ cols4,
                               const float4* __restrict__ vals4,
                               int* __restrict__ off, int2* __restrict__ cv) {
    int i = blockIdx.x * blockDim.x + threadIdx.x;
    for (; i < NNZ_E / 4; i += gridDim.x * blockDim.x) {
        int4   r = __ldg(rows4 + i);
        int4   c = __ldg(cols4 + i);
        float4 v = __ldg(vals4 + i);
        int p0 = atomicAdd(&off[r.x], 1);
        int p1 = atomicAdd(&off[r.y], 1);
        int p2 = atomicAdd(&off[r.z], 1);
        int p3 = atomicAdd(&off[r.w], 1);
        cv[p0] = make_int2(c.x, __float_as_int(v.x));
        cv[p1] = make_int2(c.y, __float_as_int(v.y));
        cv[p2] = make_int2(c.z, __float_as_int(v.z));
        cv[p3] = make_int2(c.w, __float_as_int(v.w));
    }
}

// ---------------------------------------------------------------------------
// Launches 4-7: CSR SpMM  dst = A * src  (fp16 gather via .cg, fp32 accumulate)
// Pairwise gather (R7): lanes 0-15 edge e, lanes 16-31 edge e+1; 8 B per lane.
// last layer fuses: out = 4*m1 + 5*m2 + 3*m3 + A*m3, and re-zeroes cnt.
// ---------------------------------------------------------------------------
__global__ void __launch_bounds__(256)
csr_spmm_kernel(const int* __restrict__ rowptr, const int2* __restrict__ cv,
                const uint2* __restrict__ src, uint2* __restrict__ dst,
                const uint2* __restrict__ m1, const uint2* __restrict__ m2,
                const uint2* __restrict__ m3, float4* __restrict__ out,
                int* __restrict__ cnt, int last) {
    if (last) {   // re-establish cnt==0 invariant for the next execution
        int gi = blockIdx.x * blockDim.x + threadIdx.x;
        if (gi < N_NODES) cnt[gi] = 0;
    }

    int row  = blockIdx.x * 8 + (threadIdx.x >> 5);
    int lane = threadIdx.x & 31;
    if (row >= N_NODES) return;

    int beg = __ldg(rowptr + row);
    int end = __ldg(rowptr + row + 1);

    int half = lane >> 4;    // which edge of the pair
    int sub  = lane & 15;    // which 4-dim group of the feature row

    float a0 = 0.f, a1 = 0.f, a2 = 0.f, a3 = 0.f;
    int e = beg;

    // 8 edges per iteration = 4 pairwise steps
    for (; e + 8 <= end; e += 8) {
        int2 w[4];
        #pragma unroll
        for (int k = 0; k < 4; ++k) w[k] = __ldg(cv + e + 2 * k + half);
        uint2 g[4];
        #pragma unroll
        for (int k = 0; k < 4; ++k)
            g[k] = __ldcg(src + (size_t)w[k].x * 16 + sub);
        #pragma unroll
        for (int k = 0; k < 4; ++k) {
            float v = __int_as_float(w[k].y);
            float2 p0 = __half22float2(*reinterpret_cast<__half2*>(&g[k].x));
            float2 p1 = __half22float2(*reinterpret_cast<__half2*>(&g[k].y));
            a0 = fmaf(v, p0.x, a0); a1 = fmaf(v, p0.y, a1);
            a2 = fmaf(v, p1.x, a2); a3 = fmaf(v, p1.y, a3);
        }
    }
    // masked pairwise tail
    for (; e < end; e += 2) {
        int idx = e + half;
        int2 w = __ldg(cv + (idx < end ? idx : end - 1));
        float v = (idx < end) ? __int_as_float(w.y) : 0.0f;
        uint2 g = __ldcg(src + (size_t)w.x * 16 + sub);
        float2 p0 = __half22float2(*reinterpret_cast<__half2*>(&g.x));
        float2 p1 = __half22float2(*reinterpret_cast<__half2*>(&g.y));
        a0 = fmaf(v, p0.x, a0); a1 = fmaf(v, p0.y, a1);
        a2 = fmaf(v, p1.x, a2); a3 = fmaf(v, p1.y, a3);
    }

    // merge the two half-warps
    a0 += __shfl_xor_sync(0xFFFFFFFFu, a0, 16);
    a1 += __shfl_xor_sync(0xFFFFFFFFu, a1, 16);
    a2 += __shfl_xor_sync(0xFFFFFFFFu, a2, 16);
    a3 += __shfl_xor_sync(0xFFFFFFFFu, a3, 16);

    if (half == 0) {
        size_t o = (size_t)row * 16 + sub;
        if (!last) {
            __half2 h0 = __float22half2_rn(make_float2(a0, a1));
            __half2 h1 = __float22half2_rn(make_float2(a2, a3));
            uint2 r;
            r.x = *reinterpret_cast<uint32_t*>(&h0);
            r.y = *reinterpret_cast<uint32_t*>(&h1);
            dst[o] = r;
        } else {
            uint2 q1 = __ldg(m1 + o);
            uint2 q2 = __ldg(m2 + o);
            uint2 q3 = __ldg(m3 + o);
            float2 r1a = __half22float2(*reinterpret_cast<__half2*>(&q1.x));
            float2 r1b = __half22float2(*reinterpret_cast<__half2*>(&q1.y));
            float2 r2a = __half22float2(*reinterpret_cast<__half2*>(&q2.x));
            float2 r2b = __half22float2(*reinterpret_cast<__half2*>(&q2.y));
            float2 r3a = __half22float2(*reinterpret_cast<__half2*>(&q3.x));
            float2 r3b = __half22float2(*reinterpret_cast<__half2*>(&q3.y));
            float4 ov;
            ov.x = fmaf(4.f, r1a.x, fmaf(5.f, r2a.x, fmaf(3.f, r3a.x, a0)));
            ov.y = fmaf(4.f, r1a.y, fmaf(5.f, r2a.y, fmaf(3.f, r3a.y, a1)));
            ov.z = fmaf(4.f, r1b.x, fmaf(5.f, r2b.x, fmaf(3.f, r3b.x, a2)));
            ov.w = fmaf(4.f, r1b.y, fmaf(5.f, r2b.y, fmaf(3.f, r3b.y, a3)));
            out[o] = ov;
        }
    }
}

// ---------------------------------------------------------------------------
extern "C" void kernel_launch(void* const* d_in, const int* in_sizes, int n_in,
                              void* d_out, int out_size) {
    const float* x    = (const float*)d_in[0];
    const int*   rows = (const int*)  d_in[1];
    const int*   cols = (const int*)  d_in[2];
    const float* vals = (const float*)d_in[3];
    float*       out  = (float*)d_out;

    __half *h, *m1, *m2, *m3;
    int2   *cv;
    int    *cnt, *rowptr, *off, *blksum;
    cudaGetSymbolAddress((void**)&h,      g_h);
    cudaGetSymbolAddress((void**)&m1,     g_m1);
    cudaGetSymbolAddress((void**)&m2,     g_m2);
    cudaGetSymbolAddress((void**)&m3,     g_m3);
    cudaGetSymbolAddress((void**)&cv,     g_cv);
    cudaGetSymbolAddress((void**)&cnt,    g_cnt);
    cudaGetSymbolAddress((void**)&rowptr, g_rowptr);
    cudaGetSymbolAddress((void**)&off,    g_off);
    cudaGetSymbolAddress((void**)&blksum, g_blksum);

    const int ROW_BLOCKS = (N_NODES + 7) / 8;   // 25000

    logmap_hist_kernel<<<ROW_BLOCKS, 256>>>(x, (__half2*)h, (const int4*)rows, cnt);
    scan1_kernel<<<SCAN_NBLK, 1024>>>(cnt, rowptr, blksum);
    scan3_kernel<<<256, 256>>>(rowptr, blksum, off);
    scatter_kernel<<<6250, 256>>>((const int4*)rows, (const int4*)cols,
                                  (const float4*)vals, off, cv);

    csr_spmm_kernel<<<ROW_BLOCKS, 256>>>(rowptr, cv, (const uint2*)h,  (uint2*)m1,
                                         nullptr, nullptr, nullptr, nullptr, cnt, 0);
    csr_spmm_kernel<<<ROW_BLOCKS, 256>>>(rowptr, cv, (const uint2*)m1, (uint2*)m2,
                                         nullptr, nullptr, nullptr, nullptr, cnt, 0);
    csr_spmm_kernel<<<ROW_BLOCKS, 256>>>(rowptr, cv, (const uint2*)m2, (uint2*)m3,
                                         nullptr, nullptr, nullptr, nullptr, cnt, 0);
    csr_spmm_kernel<<<ROW_BLOCKS, 256>>>(rowptr, cv, (const uint2*)m3, nullptr,
                                         (const uint2*)m1, (const uint2*)m2,
                                         (const uint2*)m3, (float4*)out, cnt, 1);
}

// round 10
// speedup vs baseline: 1.0566x; 1.0343x over previous
#include <cuda_runtime.h>
#include <cuda_fp16.h>
#include <cstdint>

#define N_NODES 200000
#define DIM     64
#define NNZ_E   6400000
#define NE      (N_NODES * DIM)
#define SCAN_CHUNK 2048
#define SCAN_NBLK  ((N_NODES + SCAN_CHUNK - 1) / SCAN_CHUNK)   // 98

// Scratch: __device__ globals (allocation-free rule). ~154 MB.
// g_cnt is zero at module load and re-zeroed by the last layer kernel of every
// execution, so each run (correctness pass + every replay) starts with cnt==0.
__device__ __half g_h[NE];              // 25.6 MB  h = logmap0(x)
__device__ __half g_m1[NE];             // 25.6 MB  m1 = A h
__device__ __half g_m2[NE];             // 25.6 MB  m2 = A m1
__device__ __half g_m3[NE];             // 25.6 MB  m3 = A m2
__device__ int2   g_cv[NNZ_E];          // 51.2 MB  (col, val-bits) row-grouped
__device__ int    g_cnt[N_NODES];
__device__ int    g_rowptr[N_NODES + 1];
__device__ int    g_off[N_NODES];
__device__ int    g_blksum[SCAN_NBLK];

// ---------------------------------------------------------------------------
// Launch 0: fused logmap0 + row histogram
// ---------------------------------------------------------------------------
__global__ void logmap_hist_kernel(const float* __restrict__ x, __half2* __restrict__ h,
                                   const int4* __restrict__ rows4, int* __restrict__ cnt) {
    int gi = blockIdx.x * blockDim.x + threadIdx.x;   // 6.4M threads
    if (gi < NNZ_E / 4) {
        int4 r = __ldg(rows4 + gi);
        atomicAdd(&cnt[r.x], 1);
        atomicAdd(&cnt[r.y], 1);
        atomicAdd(&cnt[r.z], 1);
        atomicAdd(&cnt[r.w], 1);
    }

    int row  = blockIdx.x * (blockDim.x >> 5) + (threadIdx.x >> 5);
    int lane = threadIdx.x & 31;
    if (row >= N_NODES) return;

    float2 v = reinterpret_cast<const float2*>(x + (size_t)row * DIM)[lane];
    float x0 = __shfl_sync(0xFFFFFFFFu, v.x, 0);
    float ss = v.y * v.y + (lane ? v.x * v.x : 0.0f);
    #pragma unroll
    for (int o = 16; o; o >>= 1) ss += __shfl_xor_sync(0xFFFFFFFFu, ss, o);

    float y_norm = fmaxf(sqrtf(ss), 1e-15f);
    float theta  = fmaxf(x0, 1.0f + 1e-7f);
    float s      = acoshf(theta) / y_norm;

    float2 o2;
    o2.x = lane ? s * v.x : 0.0f;
    o2.y = s * v.y;
    h[(size_t)row * 32 + lane] = __float22half2_rn(o2);
}

// ---------------------------------------------------------------------------
// Launch 1: per-block exclusive scan of 2048-chunks; totals -> blksum
// ---------------------------------------------------------------------------
__global__ void scan1_kernel(const int* __restrict__ cnt,
                             int* __restrict__ rowptr, int* __restrict__ blksum) {
    __shared__ int ws[32];
    __shared__ int carry_s;
    int tid = threadIdx.x, lane = tid & 31, wid = tid >> 5;
    int base0 = blockIdx.x * SCAN_CHUNK;
    if (tid == 0) carry_s = 0;
    __syncthreads();

    #pragma unroll
    for (int it = 0; it < SCAN_CHUNK / 1024; ++it) {
        int i = base0 + it * 1024 + tid;
        int v = (i < N_NODES) ? cnt[i] : 0;
        int x = v;
        #pragma unroll
        for (int o = 1; o < 32; o <<= 1) {
            int y = __shfl_up_sync(0xFFFFFFFFu, x, o);
            if (lane >= o) x += y;
        }
        if (lane == 31) ws[wid] = x;
        __syncthreads();
        if (wid == 0) {
            int s = ws[lane];
            #pragma unroll
            for (int o = 1; o < 32; o <<= 1) {
                int y = __shfl_up_sync(0xFFFFFFFFu, s, o);
                if (lane >= o) s += y;
            }
            ws[lane] = s;
        }
        __syncthreads();
        int carry = carry_s;
        int excl  = carry + (wid ? ws[wid - 1] : 0) + (x - v);
        if (i < N_NODES) rowptr[i] = excl;
        __syncthreads();
        if (tid == 0) carry_s = carry + ws[31];
        __syncthreads();
    }
    if (tid == 0) blksum[blockIdx.x] = carry_s;
}

// ---------------------------------------------------------------------------
// Launch 2: fused block-offset scan + apply
// ---------------------------------------------------------------------------
__global__ void scan3_kernel(int* __restrict__ rowptr, const int* __restrict__ blksum,
                             int* __restrict__ off) {
    __shared__ int boff[SCAN_NBLK];
    int tid = threadIdx.x, lane = tid & 31;
    if (tid < 32) {
        int carry = 0;
        for (int base = 0; base < SCAN_NBLK; base += 32) {
            int i = base + lane;
            int v = (i < SCAN_NBLK) ? blksum[i] : 0;
            int x = v;
            #pragma unroll
            for (int o = 1; o < 32; o <<= 1) {
                int y = __shfl_up_sync(0xFFFFFFFFu, x, o);
                if (lane >= o) x += y;
            }
            if (i < SCAN_NBLK) boff[i] = carry + x - v;
            carry += __shfl_sync(0xFFFFFFFFu, x, 31);
        }
    }
    __syncthreads();

    int i = blockIdx.x * blockDim.x + tid;
    for (; i < N_NODES; i += gridDim.x * blockDim.x) {
        int v = rowptr[i] + boff[i / SCAN_CHUNK];
        rowptr[i] = v;
        off[i]    = v;
    }
    if (blockIdx.x == 0 && tid == 0) rowptr[N_NODES] = NNZ_E;
}

// ---------------------------------------------------------------------------
// Launch 3: scatter (col,val) into row-grouped cv; 8 edges/thread (ILP-8)
// ---------------------------------------------------------------------------
__global__ void scatter_kernel(const int4* __restrict__ rows4, const int4* __restrict__ cols4,
                               const float4* __restrict__ vals4,
                               int* __restrict__ off, int2* __restrict__ cv) {
    int i = blockIdx.x * blockDim.x + threadIdx.x;
    for (; i < NNZ_E / 8; i += gridDim.x * blockDim.x) {
        int4   ra = __ldg(rows4 + 2 * i);
        int4   rb = __ldg(rows4 + 2 * i + 1);
        int4   ca = __ldg(cols4 + 2 * i);
        int4   cb = __ldg(cols4 + 2 * i + 1);
        float4 va = __ldg(vals4 + 2 * i);
        float4 vb = __ldg(vals4 + 2 * i + 1);
        // 8 independent atomic chains
        int p0 = atomicAdd(&off[ra.x], 1);
        int p1 = atomicAdd(&off[ra.y], 1);
        int p2 = atomicAdd(&off[ra.z], 1);
        int p3 = atomicAdd(&off[ra.w], 1);
        int p4 = atomicAdd(&off[rb.x], 1);
        int p5 = atomicAdd(&off[rb.y], 1);
        int p6 = atomicAdd(&off[rb.z], 1);
        int p7 = atomicAdd(&off[rb.w], 1);
        cv[p0] = make_int2(ca.x, __float_as_int(va.x));
        cv[p1] = make_int2(ca.y, __float_as_int(va.y));
        cv[p2] = make_int2(ca.z, __float_as_int(va.z));
        cv[p3] = make_int2(ca.w, __float_as_int(va.w));
        cv[p4] = make_int2(cb.x, __float_as_int(vb.x));
        cv[p5] = make_int2(cb.y, __float_as_int(vb.y));
        cv[p6] = make_int2(cb.z, __float_as_int(vb.z));
        cv[p7] = make_int2(cb.w, __float_as_int(vb.w));
    }
}

// ---------------------------------------------------------------------------
// Launches 4-7: CSR SpMM  dst = A * src  (fp16 .cg gather, fp32 accumulate)
// Pairwise gather: lanes 0-15 edge e, lanes 16-31 edge e+1; 8 B per lane.
// Main loop 16 edges/iter (8 LDG.64 in flight per lane) for latency hiding.
// last layer fuses: out = 4*m1 + 5*m2 + 3*m3 + A*m3, and re-zeroes cnt.
// ---------------------------------------------------------------------------
__global__ void __launch_bounds__(256)
csr_spmm_kernel(const int* __restrict__ rowptr, const int2* __restrict__ cv,
                const uint2* __restrict__ src, uint2* __restrict__ dst,
                const uint2* __restrict__ m1, const uint2* __restrict__ m2,
                const uint2* __restrict__ m3, float4* __restrict__ out,
                int* __restrict__ cnt, int last) {
    if (last) {
        int gi = blockIdx.x * blockDim.x + threadIdx.x;
        if (gi < N_NODES) cnt[gi] = 0;
    }

    int row  = blockIdx.x * 8 + (threadIdx.x >> 5);
    int lane = threadIdx.x & 31;
    if (row >= N_NODES) return;

    int beg = __ldg(rowptr + row);
    int end = __ldg(rowptr + row + 1);

    int half = lane >> 4;
    int sub  = lane & 15;

    float a0 = 0.f, a1 = 0.f, a2 = 0.f, a3 = 0.f;
    int e = beg;

    // 16 edges per iteration = 8 pairwise steps (deep MLP)
    for (; e + 16 <= end; e += 16) {
        int2 w[8];
        #pragma unroll
        for (int k = 0; k < 8; ++k) w[k] = __ldg(cv + e + 2 * k + half);
        uint2 g[8];
        #pragma unroll
        for (int k = 0; k < 8; ++k)
            g[k] = __ldcg(src + (size_t)w[k].x * 16 + sub);
        #pragma unroll
        for (int k = 0; k < 8; ++k) {
            float v = __int_as_float(w[k].y);
            float2 p0 = __half22float2(*reinterpret_cast<__half2*>(&g[k].x));
            float2 p1 = __half22float2(*reinterpret_cast<__half2*>(&g[k].y));
            a0 = fmaf(v, p0.x, a0); a1 = fmaf(v, p0.y, a1);
            a2 = fmaf(v, p1.x, a2); a3 = fmaf(v, p1.y, a3);
        }
    }
    // 8-edge step
    if (e + 8 <= end) {
        int2 w[4];
        #pragma unroll
        for (int k = 0; k < 4; ++k) w[k] = __ldg(cv + e + 2 * k + half);
        uint2 g[4];
        #pragma unroll
        for (int k = 0; k < 4; ++k)
            g[k] = __ldcg(src + (size_t)w[k].x * 16 + sub);
        #pragma unroll
        for (int k = 0; k < 4; ++k) {
            float v = __int_as_float(w[k].y);
            float2 p0 = __half22float2(*reinterpret_cast<__half2*>(&g[k].x));
            float2 p1 = __half22float2(*reinterpret_cast<__half2*>(&g[k].y));
            a0 = fmaf(v, p0.x, a0); a1 = fmaf(v, p0.y, a1);
            a2 = fmaf(v, p1.x, a2); a3 = fmaf(v, p1.y, a3);
        }
        e += 8;
    }
    // masked pairwise tail
    for (; e < end; e += 2) {
        int idx = e + half;
        int2 w = __ldg(cv + (idx < end ? idx : end - 1));
        float v = (idx < end) ? __int_as_float(w.y) : 0.0f;
        uint2 g = __ldcg(src + (size_t)w.x * 16 + sub);
        float2 p0 = __half22float2(*reinterpret_cast<__half2*>(&g.x));
        float2 p1 = __half22float2(*reinterpret_cast<__half2*>(&g.y));
        a0 = fmaf(v, p0.x, a0); a1 = fmaf(v, p0.y, a1);
        a2 = fmaf(v, p1.x, a2); a3 = fmaf(v, p1.y, a3);
    }

    a0 += __shfl_xor_sync(0xFFFFFFFFu, a0, 16);
    a1 += __shfl_xor_sync(0xFFFFFFFFu, a1, 16);
    a2 += __shfl_xor_sync(0xFFFFFFFFu, a2, 16);
    a3 += __shfl_xor_sync(0xFFFFFFFFu, a3, 16);

    if (half == 0) {
        size_t o = (size_t)row * 16 + sub;
        if (!last) {
            __half2 h0 = __float22half2_rn(make_float2(a0, a1));
            __half2 h1 = __float22half2_rn(make_float2(a2, a3));
            uint2 r;
            r.x = *reinterpret_cast<uint32_t*>(&h0);
            r.y = *reinterpret_cast<uint32_t*>(&h1);
            dst[o] = r;
        } else {
            uint2 q1 = __ldg(m1 + o);
            uint2 q2 = __ldg(m2 + o);
            uint2 q3 = __ldg(m3 + o);
            float2 r1a = __half22float2(*reinterpret_cast<__half2*>(&q1.x));
            float2 r1b = __half22float2(*reinterpret_cast<__half2*>(&q1.y));
            float2 r2a = __half22float2(*reinterpret_cast<__half2*>(&q2.x));
            float2 r2b = __half22float2(*reinterpret_cast<__half2*>(&q2.y));
            float2 r3a = __half22float2(*reinterpret_cast<__half2*>(&q3.x));
            float2 r3b = __half22float2(*reinterpret_cast<__half2*>(&q3.y));
            float4 ov;
            ov.x = fmaf(4.f, r1a.x, fmaf(5.f, r2a.x, fmaf(3.f, r3a.x, a0)));
            ov.y = fmaf(4.f, r1a.y, fmaf(5.f, r2a.y, fmaf(3.f, r3a.y, a1)));
            ov.z = fmaf(4.f, r1b.x, fmaf(5.f, r2b.x, fmaf(3.f, r3b.x, a2)));
            ov.w = fmaf(4.f, r1b.y, fmaf(5.f, r2b.y, fmaf(3.f, r3b.y, a3)));
            out[o] = ov;
        }
    }
}

// ---------------------------------------------------------------------------
extern "C" void kernel_launch(void* const* d_in, const int* in_sizes, int n_in,
                              void* d_out, int out_size) {
    const float* x    = (const float*)d_in[0];
    const int*   rows = (const int*)  d_in[1];
    const int*   cols = (const int*)  d_in[2];
    const float* vals = (const float*)d_in[3];
    float*       out  = (float*)d_out;

    __half *h, *m1, *m2, *m3;
    int2   *cv;
    int    *cnt, *rowptr, *off, *blksum;
    cudaGetSymbolAddress((void**)&h,      g_h);
    cudaGetSymbolAddress((void**)&m1,     g_m1);
    cudaGetSymbolAddress((void**)&m2,     g_m2);
    cudaGetSymbolAddress((void**)&m3,     g_m3);
    cudaGetSymbolAddress((void**)&cv,     g_cv);
    cudaGetSymbolAddress((void**)&cnt,    g_cnt);
    cudaGetSymbolAddress((void**)&rowptr, g_rowptr);
    cudaGetSymbolAddress((void**)&off,    g_off);
    cudaGetSymbolAddress((void**)&blksum, g_blksum);

    const int ROW_BLOCKS = (N_NODES + 7) / 8;   // 25000

    logmap_hist_kernel<<<ROW_BLOCKS, 256>>>(x, (__half2*)h, (const int4*)rows, cnt);
    scan1_kernel<<<SCAN_NBLK, 1024>>>(cnt, rowptr, blksum);
    scan3_kernel<<<256, 256>>>(rowptr, blksum, off);
    scatter_kernel<<<3125, 256>>>((const int4*)rows, (const int4*)cols,
                                  (const float4*)vals, off, cv);

    csr_spmm_kernel<<<ROW_BLOCKS, 256>>>(rowptr, cv, (const uint2*)h,  (uint2*)m1,
                                         nullptr, nullptr, nullptr, nullptr, cnt, 0);
    csr_spmm_kernel<<<ROW_BLOCKS, 256>>>(rowptr, cv, (const uint2*)m1, (uint2*)m2,
                                         nullptr, nullptr, nullptr, nullptr, cnt, 0);
    csr_spmm_kernel<<<ROW_BLOCKS, 256>>>(rowptr, cv, (const uint2*)m2, (uint2*)m3,
                                         nullptr, nullptr, nullptr, nullptr, cnt, 0);
    csr_spmm_kernel<<<ROW_BLOCKS, 256>>>(rowptr, cv, (const uint2*)m3, nullptr,
                                         (const uint2*)m1, (const uint2*)m2,
                                         (const uint2*)m3, (float4*)out, cnt, 1);
}